// round 11
// baseline (speedup 1.0000x reference)
#include <cuda_runtime.h>
#include <cuda_fp16.h>
#include <cstdint>

#define B_ 16
#define L_ 576
#define H_ 12
#define D_ 64
#define M_ 8
#define NUM_STAB 1e-3f
#define RATIO 0.35355339059327373f   /* 1/sqrt(M) */
#define NCH 24   /* cmask chunks */

// -------- scratch (device globals: no allocation allowed) --------
__device__ float g_qp[B_ * H_ * L_ * M_];           // q' fp32 [bh][l][8]
__device__ float g_cmp[NCH * H_ * L_];              // mask column-sum partials
__device__ float g_ksp[B_ * H_ * 9 * M_];           // ks partials [bh][ch][8]
__device__ __align__(16) __half g_qe[B_ * H_ * L_ * 32];  // [bh][l][32]=[qh,qh,ql,0] fp16
__device__ __align__(16) __half g_kt[B_ * H_ * 32 * L_];  // [bh][k=32][l]=[kh;kl;kh;0] fp16
__device__ __align__(16) __half g_vh[B_ * H_ * L_ * 64];  // V hi fp16
__device__ __align__(16) __half g_vl[B_ * H_ * L_ * 64];  // V lo fp16

// -------- helpers --------
__device__ __forceinline__ void ldmx4(uint32_t addr, uint32_t* r) {
    asm volatile("ldmatrix.sync.aligned.m8n8.x4.shared.b16 {%0,%1,%2,%3}, [%4];"
                 : "=r"(r[0]), "=r"(r[1]), "=r"(r[2]), "=r"(r[3]) : "r"(addr));
}
__device__ __forceinline__ void ldmx4t(uint32_t addr, uint32_t* r) {
    asm volatile("ldmatrix.sync.aligned.m8n8.x4.trans.shared.b16 {%0,%1,%2,%3}, [%4];"
                 : "=r"(r[0]), "=r"(r[1]), "=r"(r[2]), "=r"(r[3]) : "r"(addr));
}
__device__ __forceinline__ void mma16816(float* c, const uint32_t* a, const uint32_t* b) {
    asm volatile("mma.sync.aligned.m16n8k16.row.col.f32.f16.f16.f32 "
                 "{%0,%1,%2,%3}, {%4,%5,%6,%7}, {%8,%9}, {%0,%1,%2,%3};"
                 : "+f"(c[0]), "+f"(c[1]), "+f"(c[2]), "+f"(c[3])
                 : "r"(a[0]), "r"(a[1]), "r"(a[2]), "r"(a[3]), "r"(b[0]), "r"(b[1]));
}
// pack two fp32 -> f16x2; first arg -> high half (same convention as verified bf16 path)
__device__ __forceinline__ uint32_t cvtf2(float hi, float lo) {
    uint32_t r; asm("cvt.rn.f16x2.f32 %0, %1, %2;" : "=r"(r) : "f"(hi), "f"(lo)); return r;
}
__device__ __forceinline__ uint32_t smem_u32(const void* p) {
    return (uint32_t)__cvta_generic_to_shared(p);
}

// ============================================================
// Kernel 1: partial column sums of mask, 24 chunks x 24 rows (288 CTAs)
// ============================================================
__global__ void __launch_bounds__(576) cmask_part_kernel(const float* __restrict__ mask) {
    int j  = threadIdx.x;
    int h  = blockIdx.y, ch = blockIdx.x;
    const float* mp = mask + ((size_t)h * L_ + ch * 24) * L_ + j;
    float s = 0.0f;
#pragma unroll 8
    for (int i = 0; i < 24; i++) s += mp[(size_t)i * L_];
    g_cmp[(ch * H_ + h) * L_ + j] = s;
}

// ============================================================
// Kernel 2: fused prep (fp16 packing). grid (9, H, B), 128 threads.
// ============================================================
__global__ void __launch_bounds__(128) prep_kernel(const float* __restrict__ q,
                                                   const float* __restrict__ k,
                                                   const float* __restrict__ v,
                                                   const float* __restrict__ proj) {
    __shared__ float ps[8][68];
    __shared__ float xs[64][68];
    __shared__ unsigned short kt[32][64];
    __shared__ float red[64][8];
    __shared__ float cm[64];

    const int ch = blockIdx.x, h = blockIdx.y, b = blockIdx.z;
    const int bh = b * H_ + h, l0 = ch * 64;
    const int tid = threadIdx.x;
    const int r = tid >> 1, hf = tid & 1;

    {
        float4 pv = ((const float4*)proj)[tid];
        ps[tid >> 4][(tid & 15) * 4 + 0] = pv.x;
        ps[tid >> 4][(tid & 15) * 4 + 1] = pv.y;
        ps[tid >> 4][(tid & 15) * 4 + 2] = pv.z;
        ps[tid >> 4][(tid & 15) * 4 + 3] = pv.w;
    }
    if (tid < 64) {
        float s = 0.0f;
#pragma unroll
        for (int c2 = 0; c2 < NCH; c2++) s += g_cmp[(c2 * H_ + h) * L_ + l0 + tid];
        cm[tid] = s;
    }

    // ---------- Q ----------
#pragma unroll
    for (int iter = 0; iter < 8; iter++) {
        int idx = iter * 128 + tid;
        int rr = idx >> 4, c4 = idx & 15;
        float4 val = __ldg((const float4*)(q + (((size_t)b * L_ + l0 + rr) * H_ + h) * D_ + c4 * 4));
        *(float4*)&xs[rr][c4 * 4] = val;
    }
    __syncthreads();
    {
        float f[4];
#pragma unroll
        for (int e = 0; e < 4; e++) {
            int m = hf * 4 + e;
            float acc = 0.0f;
#pragma unroll
            for (int i = 0; i < 16; i++) {
                float4 a = *(const float4*)&xs[r][i * 4];
                float4 p = *(const float4*)&ps[m][i * 4];
                acc += a.x * p.x + a.y * p.y + a.z * p.z + a.w * p.w;
            }
            f[e] = fmaxf(RATIO * acc, 0.0f) + NUM_STAB;
        }
        *(float4*)(g_qp + ((size_t)bh * L_ + l0 + r) * 8 + hf * 4) = make_float4(f[0], f[1], f[2], f[3]);
        uint32_t hi2[2], lo2[2];
#pragma unroll
        for (int e = 0; e < 2; e++) {
            uint32_t hp = cvtf2(f[2 * e + 1], f[2 * e]);
            __half2 hv = *(__half2*)&hp;
            float r0 = f[2 * e]     - __low2float(hv);
            float r1 = f[2 * e + 1] - __high2float(hv);
            hi2[e] = hp;
            lo2[e] = cvtf2(r1, r0);
        }
        __half* qr = g_qe + ((size_t)bh * L_ + l0 + r) * 32;
        *(uint2*)(qr + hf * 4)      = make_uint2(hi2[0], hi2[1]);
        *(uint2*)(qr + 8 + hf * 4)  = make_uint2(hi2[0], hi2[1]);
        *(uint2*)(qr + 16 + hf * 4) = make_uint2(lo2[0], lo2[1]);
        *(uint2*)(qr + 24 + hf * 4) = make_uint2(0u, 0u);
    }
    __syncthreads();

    // ---------- K ----------
#pragma unroll
    for (int iter = 0; iter < 8; iter++) {
        int idx = iter * 128 + tid;
        int rr = idx >> 4, c4 = idx & 15;
        float4 val = __ldg((const float4*)(k + (((size_t)b * L_ + l0 + rr) * H_ + h) * D_ + c4 * 4));
        *(float4*)&xs[rr][c4 * 4] = val;
    }
    __syncthreads();
    {
        float cmv = cm[r];
#pragma unroll
        for (int e = 0; e < 4; e++) {
            int m = hf * 4 + e;
            float acc = 0.0f;
#pragma unroll
            for (int i = 0; i < 16; i++) {
                float4 a = *(const float4*)&xs[r][i * 4];
                float4 p = *(const float4*)&ps[m][i * 4];
                acc += a.x * p.x + a.y * p.y + a.z * p.z + a.w * p.w;
            }
            float f = fmaxf(RATIO * acc, 0.0f) + NUM_STAB;
            __half hh = __float2half_rn(f);
            unsigned short hs = *(unsigned short*)&hh;
            __half hl = __float2half_rn(f - __half2float(hh));
            unsigned short ls = *(unsigned short*)&hl;
            int kk = hf * 4 + e;
            kt[kk][r]      = hs;
            kt[kk + 8][r]  = ls;
            kt[kk + 16][r] = hs;
            kt[kk + 24][r] = 0;
            red[r][m] = cmv * f;
        }
    }
    __syncthreads();
    {
        int kk = tid >> 2, c = (tid & 3) * 16;
        const uint4* src = (const uint4*)&kt[kk][c];
        __half* dst = g_kt + ((size_t)bh * 32 + kk) * L_ + l0 + c;
        *(uint4*)dst       = src[0];
        *(uint4*)(dst + 8) = src[1];
    }
    if (tid < 8) {
        float s = 0.0f;
#pragma unroll 16
        for (int i = 0; i < 64; i++) s += red[i][tid];
        g_ksp[((size_t)bh * 9 + ch) * 8 + tid] = s;
    }

    // ---------- V ----------
#pragma unroll
    for (int iter = 0; iter < 8; iter++) {
        int idx = iter * 128 + tid;
        int rr = idx >> 4, c4 = idx & 15;
        const float4 vv = __ldg((const float4*)(v + (((size_t)b * L_ + l0 + rr) * H_ + h) * D_ + c4 * 4));
        float f[4] = {vv.x, vv.y, vv.z, vv.w};
        uint32_t h01 = cvtf2(f[1], f[0]);
        uint32_t h23 = cvtf2(f[3], f[2]);
        __half2 hv01 = *(__half2*)&h01;
        __half2 hv23 = *(__half2*)&h23;
        float l0f = f[0] - __low2float(hv01);
        float l1f = f[1] - __high2float(hv01);
        float l2f = f[2] - __low2float(hv23);
        float l3f = f[3] - __high2float(hv23);
        size_t o = ((size_t)bh * L_ + l0 + rr) * 64 + c4 * 4;
        *(uint2*)(g_vh + o) = make_uint2(h01, h23);
        *(uint2*)(g_vl + o) = make_uint2(cvtf2(l1f, l0f), cvtf2(l3f, l2f));
    }
}

// ============================================================
// Kernel 3: fused attention. grid (5, H, B), 256 thr / 8 warps.
// fp16 operands: S = 2 MMAs (3 cross terms), A single fp16,
// AV = Ah*Vh + Ah*Vl (2 MMAs per k-chunk).
// ============================================================
__global__ void __launch_bounds__(256, 2)
attn_kernel(const float* __restrict__ mask, float* __restrict__ out) {
    __shared__ __half Vh[64][72], Vl[64][72], Kt[32][72];
    __shared__ __half Qe[128][40];
    __shared__ float Qs[128][8];
    __shared__ float KS[8];

    const int it = blockIdx.x, h = blockIdx.y, b = blockIdx.z;
    const int i0 = it * 128, bh = b * H_ + h;
    const int tid = threadIdx.x, wid = tid >> 5, lane = tid & 31;
    const int mi = wid * 16;

    {
        int rr = tid >> 1, part = tid & 1;
        int gi = min(i0 + rr, L_ - 1);
        ((float4*)&Qs[rr][0])[part] =
            *(const float4*)(g_qp + ((size_t)bh * L_ + gi) * 8 + part * 4);
    }
    if (tid < 8) {
        float s = 0.0f;
#pragma unroll
        for (int c2 = 0; c2 < 9; c2++) s += g_ksp[((size_t)bh * 9 + c2) * 8 + tid];
        KS[tid] = s;
    }
#pragma unroll
    for (int iter = 0; iter < 2; iter++) {
        int idx = iter * 256 + tid;
        int rr = idx >> 2, c = (idx & 3) * 8;
        int gi = min(i0 + rr, L_ - 1);
        *(uint4*)&Qe[rr][c] = __ldg((const uint4*)(g_qe + ((size_t)bh * L_ + gi) * 32 + c));
    }
    __syncthreads();

    const int lq = lane >> 3, lr = lane & 7;
    const int a_row = lr + ((lq & 1) << 3);
    const int a_col = (lq & 2) << 2;
    const int vrow = ((lane >> 3) & 1) * 8 + lr;
    const int vcol = ((lane >> 4) & 1) * 8;

    const uint32_t qe_b = smem_u32(Qe);
    const uint32_t vh_b = smem_u32(Vh);
    const uint32_t vl_b = smem_u32(Vl);
    const uint32_t kt_b = smem_u32(Kt);

    uint32_t qf[2][4];
    ldmx4(qe_b + ((mi + a_row) * 40 + a_col) * 2, qf[0]);
    ldmx4(qe_b + ((mi + a_row) * 40 + 16 + a_col) * 2, qf[1]);

    float accv[8][4];
#pragma unroll
    for (int n = 0; n < 8; n++)
#pragma unroll
        for (int c = 0; c < 4; c++) accv[n][c] = 0.0f;

    const float* maskh = mask + (size_t)h * L_ * L_;
    const int r0c = min(i0 + mi + (lane >> 2), L_ - 1);
    const int r1c = min(i0 + mi + (lane >> 2) + 8, L_ - 1);

    const int v_r0 = tid >> 3,        v_c = (tid & 7) * 8;
    const int v_r1 = (256 + tid) >> 3;
    const int k_r = tid >> 3,         k_c = (tid & 7) * 8;

    uint4 pvh0, pvh1, pvl0, pvl1, pkt;
    {
        size_t o0 = ((size_t)bh * L_ + v_r0) * 64 + v_c;
        size_t o1 = ((size_t)bh * L_ + v_r1) * 64 + v_c;
        pvh0 = __ldg((const uint4*)(g_vh + o0));
        pvh1 = __ldg((const uint4*)(g_vh + o1));
        pvl0 = __ldg((const uint4*)(g_vl + o0));
        pvl1 = __ldg((const uint4*)(g_vl + o1));
        pkt  = __ldg((const uint4*)(g_kt + ((size_t)bh * 32 + k_r) * L_ + k_c));
    }

    for (int jt = 0; jt < 9; jt++) {
        const int j0 = jt * 64;
        __syncthreads();
        *(uint4*)&Vh[v_r0][v_c] = pvh0;
        *(uint4*)&Vh[v_r1][v_c] = pvh1;
        *(uint4*)&Vl[v_r0][v_c] = pvl0;
        *(uint4*)&Vl[v_r1][v_c] = pvl1;
        *(uint4*)&Kt[k_r][k_c]  = pkt;
        __syncthreads();
        if (jt < 8) {
            const int jn = j0 + 64;
            size_t o0 = ((size_t)bh * L_ + jn + v_r0) * 64 + v_c;
            size_t o1 = ((size_t)bh * L_ + jn + v_r1) * 64 + v_c;
            pvh0 = __ldg((const uint4*)(g_vh + o0));
            pvh1 = __ldg((const uint4*)(g_vh + o1));
            pvl0 = __ldg((const uint4*)(g_vl + o0));
            pvl1 = __ldg((const uint4*)(g_vl + o1));
            pkt  = __ldg((const uint4*)(g_kt + ((size_t)bh * 32 + k_r) * L_ + jn + k_c));
        }

        // ---- S via HMMA ----
        float sc[8][4];
#pragma unroll
        for (int ntp = 0; ntp < 4; ntp++) {
            uint32_t kb0[4], kb1[4];
            ldmx4t(kt_b + (vrow * 72 + ntp * 16 + vcol) * 2, kb0);
            ldmx4t(kt_b + ((16 + vrow) * 72 + ntp * 16 + vcol) * 2, kb1);
#pragma unroll
            for (int e = 0; e < 2; e++) {
                int nt = ntp * 2 + e;
                sc[nt][0] = sc[nt][1] = sc[nt][2] = sc[nt][3] = 0.0f;
                mma16816(sc[nt], qf[0], &kb0[e * 2]);
                mma16816(sc[nt], qf[1], &kb1[e * 2]);
            }
        }
        // ---- mask multiply + single fp16 round into A-frags ----
        uint32_t ah[4][4];
#pragma unroll
        for (int nt = 0; nt < 8; nt++) {
            const float* mp0 = maskh + (size_t)r0c * L_ + j0 + nt * 8 + 2 * (lane & 3);
            const float* mp1 = maskh + (size_t)r1c * L_ + j0 + nt * 8 + 2 * (lane & 3);
            float2 m0 = __ldg((const float2*)mp0);
            float2 m1 = __ldg((const float2*)mp1);
            float c0 = sc[nt][0] * m0.x, c1 = sc[nt][1] * m0.y;
            float c2 = sc[nt][2] * m1.x, c3 = sc[nt][3] * m1.y;
            int ki = nt >> 1, pspos = (nt & 1) * 2;
            ah[ki][pspos]     = cvtf2(c1, c0);
            ah[ki][pspos + 1] = cvtf2(c3, c2);
        }
        // ---- AV: D += Ah*Vh + Ah*Vl ----
#pragma unroll
        for (int ki = 0; ki < 4; ki++) {
#pragma unroll
            for (int ntp = 0; ntp < 4; ntp++) {
                uint32_t vh4[4], vl4[4];
                ldmx4t(vh_b + ((ki * 16 + vrow) * 72 + ntp * 16 + vcol) * 2, vh4);
                ldmx4t(vl_b + ((ki * 16 + vrow) * 72 + ntp * 16 + vcol) * 2, vl4);
#pragma unroll
                for (int e = 0; e < 2; e++) {
                    int nt = ntp * 2 + e;
                    mma16816(accv[nt], ah[ki], &vh4[e * 2]);
                    mma16816(accv[nt], ah[ki], &vl4[e * 2]);
                }
            }
        }
    }

    // epilogue
    const int rl = mi + (lane >> 2);
    const int gi0 = i0 + rl, gi1 = gi0 + 8;
    float n0 = 0.0f, n1 = 0.0f;
#pragma unroll
    for (int m = 0; m < 8; m++) {
        n0 += Qs[rl][m] * KS[m];
        n1 += Qs[rl + 8][m] * KS[m];
    }
    float rn0 = 1.0f / n0, rn1 = 1.0f / n1;
#pragma unroll
    for (int nt = 0; nt < 8; nt++) {
        int col = nt * 8 + 2 * (lane & 3);
        if (gi0 < L_) {
            float* o0 = out + (((size_t)b * L_ + gi0) * H_ + h) * D_ + col;
            *(float2*)o0 = make_float2(accv[nt][0] * rn0, accv[nt][1] * rn0);
        }
        if (gi1 < L_) {
            float* o1 = out + (((size_t)b * L_ + gi1) * H_ + h) * D_ + col;
            *(float2*)o1 = make_float2(accv[nt][2] * rn1, accv[nt][3] * rn1);
        }
    }
}

// ============================================================
extern "C" void kernel_launch(void* const* d_in, const int* in_sizes, int n_in,
                              void* d_out, int out_size) {
    const float* q    = (const float*)d_in[0];
    const float* k    = (const float*)d_in[1];
    const float* v    = (const float*)d_in[2];
    const float* proj = (const float*)d_in[3];
    const float* mask = (const float*)d_in[4];
    float* out = (float*)d_out;

    {
        dim3 grid(NCH, H_);
        cmask_part_kernel<<<grid, 576>>>(mask);
    }
    {
        dim3 grid(9, H_, B_);
        prep_kernel<<<grid, 128>>>(q, k, v, proj);
    }
    {
        dim3 grid(5, H_, B_);
        attn_kernel<<<grid, 256>>>(mask, out);
    }
}

// round 13
// speedup vs baseline: 1.1561x; 1.1561x over previous
#include <cuda_runtime.h>
#include <cuda_fp16.h>
#include <cstdint>

#define B_ 16
#define L_ 576
#define H_ 12
#define D_ 64
#define M_ 8
#define NUM_STAB 1e-3f
#define RATIO 0.35355339059327373f   /* 1/sqrt(M) */
#define NCH 24

// -------- scratch (device globals) --------
__device__ float g_qp[B_ * H_ * L_ * M_];
__device__ float g_cmp[NCH * H_ * L_];
__device__ float g_ksp[B_ * H_ * 9 * M_];
__device__ __align__(16) __half g_qe[B_ * H_ * L_ * 32];  // [bh][l][32]=[qh,qh,ql,0]
__device__ __align__(16) __half g_kt[B_ * H_ * 32 * L_];  // [bh][k=32][l]
__device__ __align__(16) __half g_vh[B_ * H_ * L_ * 64];
__device__ __align__(16) __half g_vl[B_ * H_ * L_ * 64];

// -------- helpers --------
__device__ __forceinline__ void ldmx4(uint32_t addr, uint32_t* r) {
    asm volatile("ldmatrix.sync.aligned.m8n8.x4.shared.b16 {%0,%1,%2,%3}, [%4];"
                 : "=r"(r[0]), "=r"(r[1]), "=r"(r[2]), "=r"(r[3]) : "r"(addr));
}
__device__ __forceinline__ void ldmx4t(uint32_t addr, uint32_t* r) {
    asm volatile("ldmatrix.sync.aligned.m8n8.x4.trans.shared.b16 {%0,%1,%2,%3}, [%4];"
                 : "=r"(r[0]), "=r"(r[1]), "=r"(r[2]), "=r"(r[3]) : "r"(addr));
}
__device__ __forceinline__ void mma16816(float* c, const uint32_t* a, const uint32_t* b) {
    asm volatile("mma.sync.aligned.m16n8k16.row.col.f32.f16.f16.f32 "
                 "{%0,%1,%2,%3}, {%4,%5,%6,%7}, {%8,%9}, {%0,%1,%2,%3};"
                 : "+f"(c[0]), "+f"(c[1]), "+f"(c[2]), "+f"(c[3])
                 : "r"(a[0]), "r"(a[1]), "r"(a[2]), "r"(a[3]), "r"(b[0]), "r"(b[1]));
}
__device__ __forceinline__ uint32_t cvtf2(float hi, float lo) {
    uint32_t r; asm("cvt.rn.f16x2.f32 %0, %1, %2;" : "=r"(r) : "f"(hi), "f"(lo)); return r;
}
__device__ __forceinline__ uint32_t smem_u32(const void* p) {
    return (uint32_t)__cvta_generic_to_shared(p);
}
__device__ __forceinline__ void cpa16(uint32_t dst, const void* src) {
    asm volatile("cp.async.cg.shared.global [%0], [%1], 16;" :: "r"(dst), "l"(src));
}
#define CP_COMMIT() asm volatile("cp.async.commit_group;" ::: "memory")
#define CP_WAIT(n)  asm volatile("cp.async.wait_group %0;" :: "n"(n) : "memory")

// smem layout (dynamic)
#define VH_SZ 9216   /* 64*72*2 */
#define KT_SZ 4608   /* 32*72*2 */
#define OFF_VH 0
#define OFF_VL (2 * VH_SZ)
#define OFF_KT (4 * VH_SZ)
#define OFF_QE (OFF_KT + 2 * KT_SZ)            /* 128*40*2 = 10240 */
#define OFF_QS (OFF_QE + 10240)                /* 128*8*4 = 4096 */
#define OFF_KS (OFF_QS + 4096)
#define SMEM_SZ (OFF_KS + 32)

// ============================================================
// Kernel 1: partial column sums of mask
// ============================================================
__global__ void __launch_bounds__(576) cmask_part_kernel(const float* __restrict__ mask) {
    int j  = threadIdx.x;
    int h  = blockIdx.y, ch = blockIdx.x;
    const float* mp = mask + ((size_t)h * L_ + ch * 24) * L_ + j;
    float s = 0.0f;
#pragma unroll 8
    for (int i = 0; i < 24; i++) s += mp[(size_t)i * L_];
    g_cmp[(ch * H_ + h) * L_ + j] = s;
}

// ============================================================
// Kernel 2: fused prep (fp16 packing) — unchanged from r11
// ============================================================
__global__ void __launch_bounds__(128) prep_kernel(const float* __restrict__ q,
                                                   const float* __restrict__ k,
                                                   const float* __restrict__ v,
                                                   const float* __restrict__ proj) {
    __shared__ float ps[8][68];
    __shared__ float xs[64][68];
    __shared__ unsigned short kt[32][64];
    __shared__ float red[64][8];
    __shared__ float cm[64];

    const int ch = blockIdx.x, h = blockIdx.y, b = blockIdx.z;
    const int bh = b * H_ + h, l0 = ch * 64;
    const int tid = threadIdx.x;
    const int r = tid >> 1, hf = tid & 1;

    {
        float4 pv = ((const float4*)proj)[tid];
        ps[tid >> 4][(tid & 15) * 4 + 0] = pv.x;
        ps[tid >> 4][(tid & 15) * 4 + 1] = pv.y;
        ps[tid >> 4][(tid & 15) * 4 + 2] = pv.z;
        ps[tid >> 4][(tid & 15) * 4 + 3] = pv.w;
    }
    if (tid < 64) {
        float s = 0.0f;
#pragma unroll
        for (int c2 = 0; c2 < NCH; c2++) s += g_cmp[(c2 * H_ + h) * L_ + l0 + tid];
        cm[tid] = s;
    }

    // Q
#pragma unroll
    for (int iter = 0; iter < 8; iter++) {
        int idx = iter * 128 + tid;
        int rr = idx >> 4, c4 = idx & 15;
        float4 val = __ldg((const float4*)(q + (((size_t)b * L_ + l0 + rr) * H_ + h) * D_ + c4 * 4));
        *(float4*)&xs[rr][c4 * 4] = val;
    }
    __syncthreads();
    {
        float f[4];
#pragma unroll
        for (int e = 0; e < 4; e++) {
            int m = hf * 4 + e;
            float acc = 0.0f;
#pragma unroll
            for (int i = 0; i < 16; i++) {
                float4 a = *(const float4*)&xs[r][i * 4];
                float4 p = *(const float4*)&ps[m][i * 4];
                acc += a.x * p.x + a.y * p.y + a.z * p.z + a.w * p.w;
            }
            f[e] = fmaxf(RATIO * acc, 0.0f) + NUM_STAB;
        }
        *(float4*)(g_qp + ((size_t)bh * L_ + l0 + r) * 8 + hf * 4) = make_float4(f[0], f[1], f[2], f[3]);
        uint32_t hi2[2], lo2[2];
#pragma unroll
        for (int e = 0; e < 2; e++) {
            uint32_t hp = cvtf2(f[2 * e + 1], f[2 * e]);
            __half2 hv = *(__half2*)&hp;
            float r0 = f[2 * e]     - __low2float(hv);
            float r1 = f[2 * e + 1] - __high2float(hv);
            hi2[e] = hp;
            lo2[e] = cvtf2(r1, r0);
        }
        __half* qr = g_qe + ((size_t)bh * L_ + l0 + r) * 32;
        *(uint2*)(qr + hf * 4)      = make_uint2(hi2[0], hi2[1]);
        *(uint2*)(qr + 8 + hf * 4)  = make_uint2(hi2[0], hi2[1]);
        *(uint2*)(qr + 16 + hf * 4) = make_uint2(lo2[0], lo2[1]);
        *(uint2*)(qr + 24 + hf * 4) = make_uint2(0u, 0u);
    }
    __syncthreads();

    // K
#pragma unroll
    for (int iter = 0; iter < 8; iter++) {
        int idx = iter * 128 + tid;
        int rr = idx >> 4, c4 = idx & 15;
        float4 val = __ldg((const float4*)(k + (((size_t)b * L_ + l0 + rr) * H_ + h) * D_ + c4 * 4));
        *(float4*)&xs[rr][c4 * 4] = val;
    }
    __syncthreads();
    {
        float cmv = cm[r];
#pragma unroll
        for (int e = 0; e < 4; e++) {
            int m = hf * 4 + e;
            float acc = 0.0f;
#pragma unroll
            for (int i = 0; i < 16; i++) {
                float4 a = *(const float4*)&xs[r][i * 4];
                float4 p = *(const float4*)&ps[m][i * 4];
                acc += a.x * p.x + a.y * p.y + a.z * p.z + a.w * p.w;
            }
            float f = fmaxf(RATIO * acc, 0.0f) + NUM_STAB;
            __half hh = __float2half_rn(f);
            unsigned short hs = *(unsigned short*)&hh;
            __half hl = __float2half_rn(f - __half2float(hh));
            unsigned short ls = *(unsigned short*)&hl;
            int kk = hf * 4 + e;
            kt[kk][r]      = hs;
            kt[kk + 8][r]  = ls;
            kt[kk + 16][r] = hs;
            kt[kk + 24][r] = 0;
            red[r][m] = cmv * f;
        }
    }
    __syncthreads();
    {
        int kk = tid >> 2, c = (tid & 3) * 16;
        const uint4* src = (const uint4*)&kt[kk][c];
        __half* dst = g_kt + ((size_t)bh * 32 + kk) * L_ + l0 + c;
        *(uint4*)dst       = src[0];
        *(uint4*)(dst + 8) = src[1];
    }
    if (tid < 8) {
        float s = 0.0f;
#pragma unroll 16
        for (int i = 0; i < 64; i++) s += red[i][tid];
        g_ksp[((size_t)bh * 9 + ch) * 8 + tid] = s;
    }

    // V
#pragma unroll
    for (int iter = 0; iter < 8; iter++) {
        int idx = iter * 128 + tid;
        int rr = idx >> 4, c4 = idx & 15;
        const float4 vv = __ldg((const float4*)(v + (((size_t)b * L_ + l0 + rr) * H_ + h) * D_ + c4 * 4));
        float f[4] = {vv.x, vv.y, vv.z, vv.w};
        uint32_t h01 = cvtf2(f[1], f[0]);
        uint32_t h23 = cvtf2(f[3], f[2]);
        __half2 hv01 = *(__half2*)&h01;
        __half2 hv23 = *(__half2*)&h23;
        float l0f = f[0] - __low2float(hv01);
        float l1f = f[1] - __high2float(hv01);
        float l2f = f[2] - __low2float(hv23);
        float l3f = f[3] - __high2float(hv23);
        size_t o = ((size_t)bh * L_ + l0 + rr) * 64 + c4 * 4;
        *(uint2*)(g_vh + o) = make_uint2(h01, h23);
        *(uint2*)(g_vl + o) = make_uint2(cvtf2(l1f, l0f), cvtf2(l3f, l2f));
    }
}

// ============================================================
// Kernel 3: fused attention. grid (5, H, B), 128 thr / 4 warps.
// Warp tile M=32; cp.async double-buffered staging.
// ============================================================
__global__ void __launch_bounds__(128, 3)
attn_kernel(const float* __restrict__ mask, float* __restrict__ out) {
    extern __shared__ char smem[];
    const uint32_t sb = smem_u32(smem);
    float* Qs = (float*)(smem + OFF_QS);
    float* KS = (float*)(smem + OFF_KS);

    const int it = blockIdx.x, h = blockIdx.y, b = blockIdx.z;
    const int i0 = it * 128, bh = b * H_ + h;
    const int tid = threadIdx.x, wid = tid >> 5, lane = tid & 31;
    const int mi = wid * 32;

    // ---- prologue staging: Qs (ONE ROW PER THREAD — covers all 128), KS, Qe ----
    {
        int gi = min(i0 + tid, L_ - 1);
        const float4* src = (const float4*)(g_qp + ((size_t)bh * L_ + gi) * 8);
        ((float4*)(Qs + tid * 8))[0] = src[0];
        ((float4*)(Qs + tid * 8))[1] = src[1];
    }
    if (tid < 8) {
        float s = 0.0f;
#pragma unroll
        for (int c2 = 0; c2 < 9; c2++) s += g_ksp[((size_t)bh * 9 + c2) * 8 + tid];
        KS[tid] = s;
    }
    {
        __half* Qe = (__half*)(smem + OFF_QE);
#pragma unroll
        for (int iter = 0; iter < 4; iter++) {
            int idx = iter * 128 + tid;
            int rr = idx >> 2, c = (idx & 3) * 8;
            int gi = min(i0 + rr, L_ - 1);
            *(uint4*)(Qe + rr * 40 + c) = __ldg((const uint4*)(g_qe + ((size_t)bh * L_ + gi) * 32 + c));
        }
    }

    const int v_row = tid >> 3, v_col = (tid & 7) * 8;
    const int k_row = tid >> 3, k_col = (tid & 7) * 8;

    // issue tile 0
    {
        const int j0 = 0, buf = 0;
        uint32_t vh_d = sb + OFF_VH + buf * VH_SZ;
        uint32_t vl_d = sb + OFF_VL + buf * VH_SZ;
        uint32_t kt_d = sb + OFF_KT + buf * KT_SZ;
#pragma unroll
        for (int i = 0; i < 4; i++) {
            int rr = v_row + i * 16;
            size_t o = ((size_t)bh * L_ + j0 + rr) * 64 + v_col;
            cpa16(vh_d + (rr * 72 + v_col) * 2, g_vh + o);
            cpa16(vl_d + (rr * 72 + v_col) * 2, g_vl + o);
        }
#pragma unroll
        for (int i = 0; i < 2; i++) {
            int rr = k_row + i * 16;
            cpa16(kt_d + (rr * 72 + k_col) * 2, g_kt + ((size_t)bh * 32 + rr) * L_ + j0 + k_col);
        }
        CP_COMMIT();
    }
    __syncthreads();   // Qe/Qs visible

    const int lq = lane >> 3, lr = lane & 7;
    const int a_row = lr + ((lq & 1) << 3);
    const int a_col = (lq & 2) << 2;
    const int vrow = ((lane >> 3) & 1) * 8 + lr;
    const int vcol = ((lane >> 4) & 1) * 8;

    uint32_t qf[2][2][4];
    {
        const uint32_t qe_b = sb + OFF_QE;
#pragma unroll
        for (int hh = 0; hh < 2; hh++) {
            ldmx4(qe_b + ((mi + hh * 16 + a_row) * 40 + a_col) * 2, qf[hh][0]);
            ldmx4(qe_b + ((mi + hh * 16 + a_row) * 40 + 16 + a_col) * 2, qf[hh][1]);
        }
    }

    float accv[2][8][4];
#pragma unroll
    for (int hh = 0; hh < 2; hh++)
#pragma unroll
        for (int n = 0; n < 8; n++)
#pragma unroll
            for (int c = 0; c < 4; c++) accv[hh][n][c] = 0.0f;

    const float* maskh = mask + (size_t)h * L_ * L_;
    int rc[4];
#pragma unroll
    for (int g = 0; g < 4; g++) rc[g] = min(i0 + mi + (lane >> 2) + g * 8, L_ - 1);

    for (int jt = 0; jt < 9; jt++) {
        const int j0 = jt * 64;
        const int buf = jt & 1;
        if (jt < 8) {
            const int jn = j0 + 64, nbuf = buf ^ 1;
            uint32_t vh_d = sb + OFF_VH + nbuf * VH_SZ;
            uint32_t vl_d = sb + OFF_VL + nbuf * VH_SZ;
            uint32_t kt_d = sb + OFF_KT + nbuf * KT_SZ;
#pragma unroll
            for (int i = 0; i < 4; i++) {
                int rr = v_row + i * 16;
                size_t o = ((size_t)bh * L_ + jn + rr) * 64 + v_col;
                cpa16(vh_d + (rr * 72 + v_col) * 2, g_vh + o);
                cpa16(vl_d + (rr * 72 + v_col) * 2, g_vl + o);
            }
#pragma unroll
            for (int i = 0; i < 2; i++) {
                int rr = k_row + i * 16;
                cpa16(kt_d + (rr * 72 + k_col) * 2, g_kt + ((size_t)bh * 32 + rr) * L_ + jn + k_col);
            }
            CP_COMMIT();
            CP_WAIT(1);
        } else {
            CP_WAIT(0);
        }
        __syncthreads();

        const uint32_t kt_b = sb + OFF_KT + buf * KT_SZ;
        const uint32_t vh_b = sb + OFF_VH + buf * VH_SZ;
        const uint32_t vl_b = sb + OFF_VL + buf * VH_SZ;

        // Kt fragments once, reused by both halves
        uint32_t kb[4][2][4];
#pragma unroll
        for (int ntp = 0; ntp < 4; ntp++) {
            ldmx4t(kt_b + (vrow * 72 + ntp * 16 + vcol) * 2, kb[ntp][0]);
            ldmx4t(kt_b + ((16 + vrow) * 72 + ntp * 16 + vcol) * 2, kb[ntp][1]);
        }
        // S + mask + pack per half
        uint32_t ah[2][4][4];
#pragma unroll
        for (int hh = 0; hh < 2; hh++) {
#pragma unroll
            for (int ntp = 0; ntp < 4; ntp++) {
#pragma unroll
                for (int e = 0; e < 2; e++) {
                    int nt = ntp * 2 + e;
                    float sc[4] = {0.0f, 0.0f, 0.0f, 0.0f};
                    mma16816(sc, qf[hh][0], &kb[ntp][0][e * 2]);
                    mma16816(sc, qf[hh][1], &kb[ntp][1][e * 2]);
                    const float* mp0 = maskh + (size_t)rc[hh * 2] * L_ + j0 + nt * 8 + 2 * (lane & 3);
                    const float* mp1 = maskh + (size_t)rc[hh * 2 + 1] * L_ + j0 + nt * 8 + 2 * (lane & 3);
                    float2 m0 = __ldg((const float2*)mp0);
                    float2 m1 = __ldg((const float2*)mp1);
                    int ki = nt >> 1, pp = (nt & 1) * 2;
                    ah[hh][ki][pp]     = cvtf2(sc[1] * m0.y, sc[0] * m0.x);
                    ah[hh][ki][pp + 1] = cvtf2(sc[3] * m1.y, sc[2] * m1.x);
                }
            }
        }
        // AV: V fragments once per ki, used by both halves
#pragma unroll
        for (int ki = 0; ki < 4; ki++) {
#pragma unroll
            for (int ntp = 0; ntp < 4; ntp++) {
                uint32_t vh4[4], vl4[4];
                ldmx4t(vh_b + ((ki * 16 + vrow) * 72 + ntp * 16 + vcol) * 2, vh4);
                ldmx4t(vl_b + ((ki * 16 + vrow) * 72 + ntp * 16 + vcol) * 2, vl4);
#pragma unroll
                for (int e = 0; e < 2; e++) {
                    int nt = ntp * 2 + e;
#pragma unroll
                    for (int hh = 0; hh < 2; hh++) {
                        mma16816(accv[hh][nt], ah[hh][ki], &vh4[e * 2]);
                        mma16816(accv[hh][nt], ah[hh][ki], &vl4[e * 2]);
                    }
                }
            }
        }
        __syncthreads();
    }

    // ---- epilogue ----
#pragma unroll
    for (int hh = 0; hh < 2; hh++) {
        int rl = mi + hh * 16 + (lane >> 2);
        int gi0 = i0 + rl, gi1 = gi0 + 8;
        float n0 = 0.0f, n1 = 0.0f;
#pragma unroll
        for (int m = 0; m < 8; m++) {
            n0 += Qs[rl * 8 + m] * KS[m];
            n1 += Qs[(rl + 8) * 8 + m] * KS[m];
        }
        float rn0 = 1.0f / n0, rn1 = 1.0f / n1;
#pragma unroll
        for (int nt = 0; nt < 8; nt++) {
            int col = nt * 8 + 2 * (lane & 3);
            if (gi0 < L_) {
                float* o0 = out + (((size_t)b * L_ + gi0) * H_ + h) * D_ + col;
                *(float2*)o0 = make_float2(accv[hh][nt][0] * rn0, accv[hh][nt][1] * rn0);
            }
            if (gi1 < L_) {
                float* o1 = out + (((size_t)b * L_ + gi1) * H_ + h) * D_ + col;
                *(float2*)o1 = make_float2(accv[hh][nt][2] * rn1, accv[hh][nt][3] * rn1);
            }
        }
    }
}

// ============================================================
extern "C" void kernel_launch(void* const* d_in, const int* in_sizes, int n_in,
                              void* d_out, int out_size) {
    const float* q    = (const float*)d_in[0];
    const float* k    = (const float*)d_in[1];
    const float* v    = (const float*)d_in[2];
    const float* proj = (const float*)d_in[3];
    const float* mask = (const float*)d_in[4];
    float* out = (float*)d_out;

    cudaFuncSetAttribute(attn_kernel, cudaFuncAttributeMaxDynamicSharedMemorySize, SMEM_SZ);

    {
        dim3 grid(NCH, H_);
        cmask_part_kernel<<<grid, 576>>>(mask);
    }
    {
        dim3 grid(9, H_, B_);
        prep_kernel<<<grid, 128>>>(q, k, v, proj);
    }
    {
        dim3 grid(5, H_, B_);
        attn_kernel<<<grid, 128, SMEM_SZ>>>(mask, out);
    }
}

// round 14
// speedup vs baseline: 1.3923x; 1.2042x over previous
#include <cuda_runtime.h>
#include <cuda_fp16.h>
#include <cstdint>

#define B_ 16
#define L_ 576
#define H_ 12
#define D_ 64
#define M_ 8
#define NUM_STAB 1e-3f
#define RATIO 0.35355339059327373f   /* 1/sqrt(M) */
#define NCH 24

// -------- scratch (device globals) --------
__device__ float g_qp[B_ * H_ * L_ * M_];
__device__ float g_cmp[NCH * H_ * L_];
__device__ float g_ksp[B_ * H_ * 9 * M_];
__device__ __align__(16) __half g_qe[B_ * H_ * L_ * 32];  // [bh][l][32]=[qh,qh,ql,0]
__device__ __align__(16) __half g_kt[B_ * H_ * 32 * L_];  // [bh][k=32][l]
__device__ __align__(16) __half g_vh[B_ * H_ * L_ * 64];  // V fp16

// -------- helpers --------
__device__ __forceinline__ void ldmx4(uint32_t addr, uint32_t* r) {
    asm volatile("ldmatrix.sync.aligned.m8n8.x4.shared.b16 {%0,%1,%2,%3}, [%4];"
                 : "=r"(r[0]), "=r"(r[1]), "=r"(r[2]), "=r"(r[3]) : "r"(addr));
}
__device__ __forceinline__ void ldmx4t(uint32_t addr, uint32_t* r) {
    asm volatile("ldmatrix.sync.aligned.m8n8.x4.trans.shared.b16 {%0,%1,%2,%3}, [%4];"
                 : "=r"(r[0]), "=r"(r[1]), "=r"(r[2]), "=r"(r[3]) : "r"(addr));
}
__device__ __forceinline__ void mma16816(float* c, const uint32_t* a, const uint32_t* b) {
    asm volatile("mma.sync.aligned.m16n8k16.row.col.f32.f16.f16.f32 "
                 "{%0,%1,%2,%3}, {%4,%5,%6,%7}, {%8,%9}, {%0,%1,%2,%3};"
                 : "+f"(c[0]), "+f"(c[1]), "+f"(c[2]), "+f"(c[3])
                 : "r"(a[0]), "r"(a[1]), "r"(a[2]), "r"(a[3]), "r"(b[0]), "r"(b[1]));
}
__device__ __forceinline__ uint32_t cvtf2(float hi, float lo) {
    uint32_t r; asm("cvt.rn.f16x2.f32 %0, %1, %2;" : "=r"(r) : "f"(hi), "f"(lo)); return r;
}
__device__ __forceinline__ uint32_t smem_u32(const void* p) {
    return (uint32_t)__cvta_generic_to_shared(p);
}
__device__ __forceinline__ void cpa16(uint32_t dst, const void* src) {
    asm volatile("cp.async.cg.shared.global [%0], [%1], 16;" :: "r"(dst), "l"(src));
}
#define CP_COMMIT() asm volatile("cp.async.commit_group;" ::: "memory")
#define CP_WAIT(n)  asm volatile("cp.async.wait_group %0;" :: "n"(n) : "memory")

// smem layout (dynamic)
#define VH_SZ 9216   /* 64*72*2 */
#define KT_SZ 4608   /* 32*72*2 */
#define OFF_VH 0
#define OFF_KT (2 * VH_SZ)
#define OFF_QE (OFF_KT + 2 * KT_SZ)            /* 128*40*2 = 10240 */
#define OFF_QS (OFF_QE + 10240)                /* 128*8*4 = 4096 */
#define OFF_KS (OFF_QS + 4096)
#define SMEM_SZ (OFF_KS + 32)

// ============================================================
// Kernel 1: partial column sums of mask
// ============================================================
__global__ void __launch_bounds__(576) cmask_part_kernel(const float* __restrict__ mask) {
    int j  = threadIdx.x;
    int h  = blockIdx.y, ch = blockIdx.x;
    const float* mp = mask + ((size_t)h * L_ + ch * 24) * L_ + j;
    float s = 0.0f;
#pragma unroll 8
    for (int i = 0; i < 24; i++) s += mp[(size_t)i * L_];
    g_cmp[(ch * H_ + h) * L_ + j] = s;
}

// ============================================================
// Kernel 2: fused prep (fp16 packing; V hi only)
// ============================================================
__global__ void __launch_bounds__(128) prep_kernel(const float* __restrict__ q,
                                                   const float* __restrict__ k,
                                                   const float* __restrict__ v,
                                                   const float* __restrict__ proj) {
    __shared__ float ps[8][68];
    __shared__ float xs[64][68];
    __shared__ unsigned short kt[32][64];
    __shared__ float red[64][8];
    __shared__ float cm[64];

    const int ch = blockIdx.x, h = blockIdx.y, b = blockIdx.z;
    const int bh = b * H_ + h, l0 = ch * 64;
    const int tid = threadIdx.x;
    const int r = tid >> 1, hf = tid & 1;

    {
        float4 pv = ((const float4*)proj)[tid];
        ps[tid >> 4][(tid & 15) * 4 + 0] = pv.x;
        ps[tid >> 4][(tid & 15) * 4 + 1] = pv.y;
        ps[tid >> 4][(tid & 15) * 4 + 2] = pv.z;
        ps[tid >> 4][(tid & 15) * 4 + 3] = pv.w;
    }
    if (tid < 64) {
        float s = 0.0f;
#pragma unroll
        for (int c2 = 0; c2 < NCH; c2++) s += g_cmp[(c2 * H_ + h) * L_ + l0 + tid];
        cm[tid] = s;
    }

    // Q
#pragma unroll
    for (int iter = 0; iter < 8; iter++) {
        int idx = iter * 128 + tid;
        int rr = idx >> 4, c4 = idx & 15;
        float4 val = __ldg((const float4*)(q + (((size_t)b * L_ + l0 + rr) * H_ + h) * D_ + c4 * 4));
        *(float4*)&xs[rr][c4 * 4] = val;
    }
    __syncthreads();
    {
        float f[4];
#pragma unroll
        for (int e = 0; e < 4; e++) {
            int m = hf * 4 + e;
            float acc = 0.0f;
#pragma unroll
            for (int i = 0; i < 16; i++) {
                float4 a = *(const float4*)&xs[r][i * 4];
                float4 p = *(const float4*)&ps[m][i * 4];
                acc += a.x * p.x + a.y * p.y + a.z * p.z + a.w * p.w;
            }
            f[e] = fmaxf(RATIO * acc, 0.0f) + NUM_STAB;
        }
        *(float4*)(g_qp + ((size_t)bh * L_ + l0 + r) * 8 + hf * 4) = make_float4(f[0], f[1], f[2], f[3]);
        uint32_t hi2[2], lo2[2];
#pragma unroll
        for (int e = 0; e < 2; e++) {
            uint32_t hp = cvtf2(f[2 * e + 1], f[2 * e]);
            __half2 hv = *(__half2*)&hp;
            float r0 = f[2 * e]     - __low2float(hv);
            float r1 = f[2 * e + 1] - __high2float(hv);
            hi2[e] = hp;
            lo2[e] = cvtf2(r1, r0);
        }
        __half* qr = g_qe + ((size_t)bh * L_ + l0 + r) * 32;
        *(uint2*)(qr + hf * 4)      = make_uint2(hi2[0], hi2[1]);
        *(uint2*)(qr + 8 + hf * 4)  = make_uint2(hi2[0], hi2[1]);
        *(uint2*)(qr + 16 + hf * 4) = make_uint2(lo2[0], lo2[1]);
        *(uint2*)(qr + 24 + hf * 4) = make_uint2(0u, 0u);
    }
    __syncthreads();

    // K
#pragma unroll
    for (int iter = 0; iter < 8; iter++) {
        int idx = iter * 128 + tid;
        int rr = idx >> 4, c4 = idx & 15;
        float4 val = __ldg((const float4*)(k + (((size_t)b * L_ + l0 + rr) * H_ + h) * D_ + c4 * 4));
        *(float4*)&xs[rr][c4 * 4] = val;
    }
    __syncthreads();
    {
        float cmv = cm[r];
#pragma unroll
        for (int e = 0; e < 4; e++) {
            int m = hf * 4 + e;
            float acc = 0.0f;
#pragma unroll
            for (int i = 0; i < 16; i++) {
                float4 a = *(const float4*)&xs[r][i * 4];
                float4 p = *(const float4*)&ps[m][i * 4];
                acc += a.x * p.x + a.y * p.y + a.z * p.z + a.w * p.w;
            }
            float f = fmaxf(RATIO * acc, 0.0f) + NUM_STAB;
            __half hh = __float2half_rn(f);
            unsigned short hs = *(unsigned short*)&hh;
            __half hl = __float2half_rn(f - __half2float(hh));
            unsigned short ls = *(unsigned short*)&hl;
            int kk = hf * 4 + e;
            kt[kk][r]      = hs;
            kt[kk + 8][r]  = ls;
            kt[kk + 16][r] = hs;
            kt[kk + 24][r] = 0;
            red[r][m] = cmv * f;
        }
    }
    __syncthreads();
    {
        int kk = tid >> 2, c = (tid & 3) * 16;
        const uint4* src = (const uint4*)&kt[kk][c];
        __half* dst = g_kt + ((size_t)bh * 32 + kk) * L_ + l0 + c;
        *(uint4*)dst       = src[0];
        *(uint4*)(dst + 8) = src[1];
    }
    if (tid < 8) {
        float s = 0.0f;
#pragma unroll 16
        for (int i = 0; i < 64; i++) s += red[i][tid];
        g_ksp[((size_t)bh * 9 + ch) * 8 + tid] = s;
    }

    // V (hi only)
#pragma unroll
    for (int iter = 0; iter < 8; iter++) {
        int idx = iter * 128 + tid;
        int rr = idx >> 4, c4 = idx & 15;
        const float4 vv = __ldg((const float4*)(v + (((size_t)b * L_ + l0 + rr) * H_ + h) * D_ + c4 * 4));
        uint32_t h01 = cvtf2(vv.y, vv.x);
        uint32_t h23 = cvtf2(vv.w, vv.z);
        size_t o = ((size_t)bh * L_ + l0 + rr) * 64 + c4 * 4;
        *(uint2*)(g_vh + o) = make_uint2(h01, h23);
    }
}

// ============================================================
// Kernel 3: fused attention. grid (5, H, B), 128 thr / 4 warps.
// Warp tile M=32; cp.async double-buffered; AV = Ah*Vh only.
// ============================================================
__global__ void __launch_bounds__(128, 3)
attn_kernel(const float* __restrict__ mask, float* __restrict__ out) {
    extern __shared__ char smem[];
    const uint32_t sb = smem_u32(smem);
    float* Qs = (float*)(smem + OFF_QS);
    float* KS = (float*)(smem + OFF_KS);

    const int it = blockIdx.x, h = blockIdx.y, b = blockIdx.z;
    const int i0 = it * 128, bh = b * H_ + h;
    const int tid = threadIdx.x, wid = tid >> 5, lane = tid & 31;
    const int mi = wid * 32;

    // ---- prologue staging: Qs (one row per thread), KS, Qe ----
    {
        int gi = min(i0 + tid, L_ - 1);
        const float4* src = (const float4*)(g_qp + ((size_t)bh * L_ + gi) * 8);
        ((float4*)(Qs + tid * 8))[0] = src[0];
        ((float4*)(Qs + tid * 8))[1] = src[1];
    }
    if (tid < 8) {
        float s = 0.0f;
#pragma unroll
        for (int c2 = 0; c2 < 9; c2++) s += g_ksp[((size_t)bh * 9 + c2) * 8 + tid];
        KS[tid] = s;
    }
    {
        __half* Qe = (__half*)(smem + OFF_QE);
#pragma unroll
        for (int iter = 0; iter < 4; iter++) {
            int idx = iter * 128 + tid;
            int rr = idx >> 2, c = (idx & 3) * 8;
            int gi = min(i0 + rr, L_ - 1);
            *(uint4*)(Qe + rr * 40 + c) = __ldg((const uint4*)(g_qe + ((size_t)bh * L_ + gi) * 32 + c));
        }
    }

    const int v_row = tid >> 3, v_col = (tid & 7) * 8;
    const int k_row = tid >> 3, k_col = (tid & 7) * 8;

    // issue tile 0
    {
        const int j0 = 0, buf = 0;
        uint32_t vh_d = sb + OFF_VH + buf * VH_SZ;
        uint32_t kt_d = sb + OFF_KT + buf * KT_SZ;
#pragma unroll
        for (int i = 0; i < 4; i++) {
            int rr = v_row + i * 16;
            cpa16(vh_d + (rr * 72 + v_col) * 2, g_vh + ((size_t)bh * L_ + j0 + rr) * 64 + v_col);
        }
#pragma unroll
        for (int i = 0; i < 2; i++) {
            int rr = k_row + i * 16;
            cpa16(kt_d + (rr * 72 + k_col) * 2, g_kt + ((size_t)bh * 32 + rr) * L_ + j0 + k_col);
        }
        CP_COMMIT();
    }
    __syncthreads();   // Qe/Qs visible

    const int lq = lane >> 3, lr = lane & 7;
    const int a_row = lr + ((lq & 1) << 3);
    const int a_col = (lq & 2) << 2;
    const int vrow = ((lane >> 3) & 1) * 8 + lr;
    const int vcol = ((lane >> 4) & 1) * 8;

    uint32_t qf[2][2][4];
    {
        const uint32_t qe_b = sb + OFF_QE;
#pragma unroll
        for (int hh = 0; hh < 2; hh++) {
            ldmx4(qe_b + ((mi + hh * 16 + a_row) * 40 + a_col) * 2, qf[hh][0]);
            ldmx4(qe_b + ((mi + hh * 16 + a_row) * 40 + 16 + a_col) * 2, qf[hh][1]);
        }
    }

    float accv[2][8][4];
#pragma unroll
    for (int hh = 0; hh < 2; hh++)
#pragma unroll
        for (int n = 0; n < 8; n++)
#pragma unroll
            for (int c = 0; c < 4; c++) accv[hh][n][c] = 0.0f;

    const float* maskh = mask + (size_t)h * L_ * L_;
    int rc[4];
#pragma unroll
    for (int g = 0; g < 4; g++) rc[g] = min(i0 + mi + (lane >> 2) + g * 8, L_ - 1);

    for (int jt = 0; jt < 9; jt++) {
        const int j0 = jt * 64;
        const int buf = jt & 1;
        if (jt < 8) {
            const int jn = j0 + 64, nbuf = buf ^ 1;
            uint32_t vh_d = sb + OFF_VH + nbuf * VH_SZ;
            uint32_t kt_d = sb + OFF_KT + nbuf * KT_SZ;
#pragma unroll
            for (int i = 0; i < 4; i++) {
                int rr = v_row + i * 16;
                cpa16(vh_d + (rr * 72 + v_col) * 2, g_vh + ((size_t)bh * L_ + jn + rr) * 64 + v_col);
            }
#pragma unroll
            for (int i = 0; i < 2; i++) {
                int rr = k_row + i * 16;
                cpa16(kt_d + (rr * 72 + k_col) * 2, g_kt + ((size_t)bh * 32 + rr) * L_ + jn + k_col);
            }
            CP_COMMIT();
            CP_WAIT(1);
        } else {
            CP_WAIT(0);
        }
        __syncthreads();

        const uint32_t kt_b = sb + OFF_KT + buf * KT_SZ;
        const uint32_t vh_b = sb + OFF_VH + buf * VH_SZ;

        // Kt fragments once, reused by both halves
        uint32_t kb[4][2][4];
#pragma unroll
        for (int ntp = 0; ntp < 4; ntp++) {
            ldmx4t(kt_b + (vrow * 72 + ntp * 16 + vcol) * 2, kb[ntp][0]);
            ldmx4t(kt_b + ((16 + vrow) * 72 + ntp * 16 + vcol) * 2, kb[ntp][1]);
        }
        // S + mask + pack per half
        uint32_t ah[2][4][4];
#pragma unroll
        for (int hh = 0; hh < 2; hh++) {
#pragma unroll
            for (int ntp = 0; ntp < 4; ntp++) {
#pragma unroll
                for (int e = 0; e < 2; e++) {
                    int nt = ntp * 2 + e;
                    float sc[4] = {0.0f, 0.0f, 0.0f, 0.0f};
                    mma16816(sc, qf[hh][0], &kb[ntp][0][e * 2]);
                    mma16816(sc, qf[hh][1], &kb[ntp][1][e * 2]);
                    const float* mp0 = maskh + (size_t)rc[hh * 2] * L_ + j0 + nt * 8 + 2 * (lane & 3);
                    const float* mp1 = maskh + (size_t)rc[hh * 2 + 1] * L_ + j0 + nt * 8 + 2 * (lane & 3);
                    float2 m0 = __ldg((const float2*)mp0);
                    float2 m1 = __ldg((const float2*)mp1);
                    int ki = nt >> 1, pp = (nt & 1) * 2;
                    ah[hh][ki][pp]     = cvtf2(sc[1] * m0.y, sc[0] * m0.x);
                    ah[hh][ki][pp + 1] = cvtf2(sc[3] * m1.y, sc[2] * m1.x);
                }
            }
        }
        // AV: D += Ah*Vh
#pragma unroll
        for (int ki = 0; ki < 4; ki++) {
#pragma unroll
            for (int ntp = 0; ntp < 4; ntp++) {
                uint32_t vh4[4];
                ldmx4t(vh_b + ((ki * 16 + vrow) * 72 + ntp * 16 + vcol) * 2, vh4);
#pragma unroll
                for (int e = 0; e < 2; e++) {
                    int nt = ntp * 2 + e;
#pragma unroll
                    for (int hh = 0; hh < 2; hh++) {
                        mma16816(accv[hh][nt], ah[hh][ki], &vh4[e * 2]);
                    }
                }
            }
        }
        __syncthreads();
    }

    // ---- epilogue ----
#pragma unroll
    for (int hh = 0; hh < 2; hh++) {
        int rl = mi + hh * 16 + (lane >> 2);
        int gi0 = i0 + rl, gi1 = gi0 + 8;
        float n0 = 0.0f, n1 = 0.0f;
#pragma unroll
        for (int m = 0; m < 8; m++) {
            n0 += Qs[rl * 8 + m] * KS[m];
            n1 += Qs[(rl + 8) * 8 + m] * KS[m];
        }
        float rn0 = 1.0f / n0, rn1 = 1.0f / n1;
#pragma unroll
        for (int nt = 0; nt < 8; nt++) {
            int col = nt * 8 + 2 * (lane & 3);
            if (gi0 < L_) {
                float* o0 = out + (((size_t)b * L_ + gi0) * H_ + h) * D_ + col;
                *(float2*)o0 = make_float2(accv[hh][nt][0] * rn0, accv[hh][nt][1] * rn0);
            }
            if (gi1 < L_) {
                float* o1 = out + (((size_t)b * L_ + gi1) * H_ + h) * D_ + col;
                *(float2*)o1 = make_float2(accv[hh][nt][2] * rn1, accv[hh][nt][3] * rn1);
            }
        }
    }
}

// ============================================================
extern "C" void kernel_launch(void* const* d_in, const int* in_sizes, int n_in,
                              void* d_out, int out_size) {
    const float* q    = (const float*)d_in[0];
    const float* k    = (const float*)d_in[1];
    const float* v    = (const float*)d_in[2];
    const float* proj = (const float*)d_in[3];
    const float* mask = (const float*)d_in[4];
    float* out = (float*)d_out;

    cudaFuncSetAttribute(attn_kernel, cudaFuncAttributeMaxDynamicSharedMemorySize, SMEM_SZ);

    {
        dim3 grid(NCH, H_);
        cmask_part_kernel<<<grid, 576>>>(mask);
    }
    {
        dim3 grid(9, H_, B_);
        prep_kernel<<<grid, 128>>>(q, k, v, proj);
    }
    {
        dim3 grid(5, H_, B_);
        attn_kernel<<<grid, 128, SMEM_SZ>>>(mask, out);
    }
}

// round 16
// speedup vs baseline: 1.5066x; 1.0821x over previous
#include <cuda_runtime.h>
#include <cuda_fp16.h>
#include <cstdint>

#define B_ 16
#define L_ 576
#define H_ 12
#define D_ 64
#define M_ 8
#define NUM_STAB 1e-3f
#define RATIO 0.35355339059327373f   /* 1/sqrt(M) */
#define NCH 48

// -------- scratch (device globals) --------
__device__ float g_qp[B_ * H_ * L_ * M_];
__device__ float g_cmp[NCH * H_ * L_];
__device__ float g_ksp[B_ * H_ * 9 * M_];
__device__ __align__(16) __half g_qe[B_ * H_ * L_ * 16];  // [bh][l][16]=[qh,qh]
__device__ __align__(16) __half g_kt[B_ * H_ * 16 * L_];  // [bh][k=16][l]=[kh;kl]
__device__ __align__(16) __half g_vh[B_ * H_ * L_ * 64];  // V fp16

// -------- helpers --------
__device__ __forceinline__ void ldmx4(uint32_t addr, uint32_t* r) {
    asm volatile("ldmatrix.sync.aligned.m8n8.x4.shared.b16 {%0,%1,%2,%3}, [%4];"
                 : "=r"(r[0]), "=r"(r[1]), "=r"(r[2]), "=r"(r[3]) : "r"(addr));
}
__device__ __forceinline__ void ldmx4t(uint32_t addr, uint32_t* r) {
    asm volatile("ldmatrix.sync.aligned.m8n8.x4.trans.shared.b16 {%0,%1,%2,%3}, [%4];"
                 : "=r"(r[0]), "=r"(r[1]), "=r"(r[2]), "=r"(r[3]) : "r"(addr));
}
__device__ __forceinline__ void mma16816(float* c, const uint32_t* a, const uint32_t* b) {
    asm volatile("mma.sync.aligned.m16n8k16.row.col.f32.f16.f16.f32 "
                 "{%0,%1,%2,%3}, {%4,%5,%6,%7}, {%8,%9}, {%0,%1,%2,%3};"
                 : "+f"(c[0]), "+f"(c[1]), "+f"(c[2]), "+f"(c[3])
                 : "r"(a[0]), "r"(a[1]), "r"(a[2]), "r"(a[3]), "r"(b[0]), "r"(b[1]));
}
__device__ __forceinline__ uint32_t cvtf2(float hi, float lo) {
    uint32_t r; asm("cvt.rn.f16x2.f32 %0, %1, %2;" : "=r"(r) : "f"(hi), "f"(lo)); return r;
}
__device__ __forceinline__ uint32_t smem_u32(const void* p) {
    return (uint32_t)__cvta_generic_to_shared(p);
}
__device__ __forceinline__ void cpa16(uint32_t dst, const void* src) {
    asm volatile("cp.async.cg.shared.global [%0], [%1], 16;" :: "r"(dst), "l"(src));
}
#define CP_COMMIT() asm volatile("cp.async.commit_group;" ::: "memory")
#define CP_WAIT(n)  asm volatile("cp.async.wait_group %0;" :: "n"(n) : "memory")

// smem layout (dynamic)
#define VH_SZ 9216   /* 64*72*2 */
#define KT_SZ 2304   /* 16*72*2 */
#define OFF_VH 0
#define OFF_KT (2 * VH_SZ)                     /* 18432 */
#define OFF_QE (OFF_KT + 2 * KT_SZ)            /* 23040; 128*24*2 = 6144 */
#define OFF_QS (OFF_QE + 6144)                 /* 29184; 128*8*4 = 4096 */
#define OFF_KS (OFF_QS + 4096)
#define SMEM_SZ (OFF_KS + 32)

// ============================================================
// Kernel 1: partial column sums of mask, 48 chunks x 12 rows (576 CTAs)
// ============================================================
__global__ void __launch_bounds__(576) cmask_part_kernel(const float* __restrict__ mask) {
    int j  = threadIdx.x;
    int h  = blockIdx.y, ch = blockIdx.x;
    const float* mp = mask + ((size_t)h * L_ + ch * 12) * L_ + j;
    float s = 0.0f;
#pragma unroll
    for (int i = 0; i < 12; i++) s += mp[(size_t)i * L_];
    g_cmp[(ch * H_ + h) * L_ + j] = s;
}

// ============================================================
// Kernel 2: fused prep (fp16; Qe=[qh,qh], Kt=[kh;kl], V hi only)
// ============================================================
__global__ void __launch_bounds__(128) prep_kernel(const float* __restrict__ q,
                                                   const float* __restrict__ k,
                                                   const float* __restrict__ v,
                                                   const float* __restrict__ proj) {
    __shared__ float ps[8][68];
    __shared__ float xs[64][68];
    __shared__ unsigned short kt[16][64];
    __shared__ float red[64][8];
    __shared__ float cm[64];

    const int ch = blockIdx.x, h = blockIdx.y, b = blockIdx.z;
    const int bh = b * H_ + h, l0 = ch * 64;
    const int tid = threadIdx.x;
    const int r = tid >> 1, hf = tid & 1;

    {
        float4 pv = ((const float4*)proj)[tid];
        ps[tid >> 4][(tid & 15) * 4 + 0] = pv.x;
        ps[tid >> 4][(tid & 15) * 4 + 1] = pv.y;
        ps[tid >> 4][(tid & 15) * 4 + 2] = pv.z;
        ps[tid >> 4][(tid & 15) * 4 + 3] = pv.w;
    }
    if (tid < 64) {
        float s = 0.0f;
#pragma unroll
        for (int c2 = 0; c2 < NCH; c2++) s += g_cmp[(c2 * H_ + h) * L_ + l0 + tid];
        cm[tid] = s;
    }

    // ---------- Q ----------
#pragma unroll
    for (int iter = 0; iter < 8; iter++) {
        int idx = iter * 128 + tid;
        int rr = idx >> 4, c4 = idx & 15;
        float4 val = __ldg((const float4*)(q + (((size_t)b * L_ + l0 + rr) * H_ + h) * D_ + c4 * 4));
        *(float4*)&xs[rr][c4 * 4] = val;
    }
    __syncthreads();
    {
        float f[4];
#pragma unroll
        for (int e = 0; e < 4; e++) {
            int m = hf * 4 + e;
            float acc = 0.0f;
#pragma unroll
            for (int i = 0; i < 16; i++) {
                float4 a = *(const float4*)&xs[r][i * 4];
                float4 p = *(const float4*)&ps[m][i * 4];
                acc += a.x * p.x + a.y * p.y + a.z * p.z + a.w * p.w;
            }
            f[e] = fmaxf(RATIO * acc, 0.0f) + NUM_STAB;
        }
        *(float4*)(g_qp + ((size_t)bh * L_ + l0 + r) * 8 + hf * 4) = make_float4(f[0], f[1], f[2], f[3]);
        uint32_t hi0 = cvtf2(f[1], f[0]);
        uint32_t hi1 = cvtf2(f[3], f[2]);
        __half* qr = g_qe + ((size_t)bh * L_ + l0 + r) * 16;
        *(uint2*)(qr + hf * 4)     = make_uint2(hi0, hi1);
        *(uint2*)(qr + 8 + hf * 4) = make_uint2(hi0, hi1);
    }
    __syncthreads();

    // ---------- K ----------
#pragma unroll
    for (int iter = 0; iter < 8; iter++) {
        int idx = iter * 128 + tid;
        int rr = idx >> 4, c4 = idx & 15;
        float4 val = __ldg((const float4*)(k + (((size_t)b * L_ + l0 + rr) * H_ + h) * D_ + c4 * 4));
        *(float4*)&xs[rr][c4 * 4] = val;
    }
    __syncthreads();
    {
        float cmv = cm[r];
#pragma unroll
        for (int e = 0; e < 4; e++) {
            int m = hf * 4 + e;
            float acc = 0.0f;
#pragma unroll
            for (int i = 0; i < 16; i++) {
                float4 a = *(const float4*)&xs[r][i * 4];
                float4 p = *(const float4*)&ps[m][i * 4];
                acc += a.x * p.x + a.y * p.y + a.z * p.z + a.w * p.w;
            }
            float f = fmaxf(RATIO * acc, 0.0f) + NUM_STAB;
            __half hh = __float2half_rn(f);
            unsigned short hs = *(unsigned short*)&hh;
            __half hl = __float2half_rn(f - __half2float(hh));
            unsigned short ls = *(unsigned short*)&hl;
            int kk = hf * 4 + e;
            kt[kk][r]     = hs;
            kt[kk + 8][r] = ls;
            red[r][m] = cmv * f;
        }
    }
    __syncthreads();
    // Kt rows -> gmem: 16 rows x 64 cols, one uint4 per thread
    {
        int kk = tid >> 3, c = (tid & 7) * 8;
        *(uint4*)(g_kt + ((size_t)bh * 16 + kk) * L_ + l0 + c) = *(const uint4*)&kt[kk][c];
    }
    if (tid < 8) {
        float s = 0.0f;
#pragma unroll 16
        for (int i = 0; i < 64; i++) s += red[i][tid];
        g_ksp[((size_t)bh * 9 + ch / (64 / 64) /*ch*/) * 8 + tid] = s;
    }

    // ---------- V (hi only) ----------
#pragma unroll
    for (int iter = 0; iter < 8; iter++) {
        int idx = iter * 128 + tid;
        int rr = idx >> 4, c4 = idx & 15;
        const float4 vv = __ldg((const float4*)(v + (((size_t)b * L_ + l0 + rr) * H_ + h) * D_ + c4 * 4));
        uint32_t h01 = cvtf2(vv.y, vv.x);
        uint32_t h23 = cvtf2(vv.w, vv.z);
        size_t o = ((size_t)bh * L_ + l0 + rr) * 64 + c4 * 4;
        *(uint2*)(g_vh + o) = make_uint2(h01, h23);
    }
}

// ============================================================
// Kernel 3: fused attention. grid (5, H, B), 128 thr / 4 warps.
// Warp tile M=32; cp.async double-buffered; S = 1 MMA (qh x [kh;kl]);
// AV = Ah*Vh.
// ============================================================
__global__ void __launch_bounds__(128, 3)
attn_kernel(const float* __restrict__ mask, float* __restrict__ out) {
    extern __shared__ char smem[];
    const uint32_t sb = smem_u32(smem);
    float* Qs = (float*)(smem + OFF_QS);
    float* KS = (float*)(smem + OFF_KS);

    const int it = blockIdx.x, h = blockIdx.y, b = blockIdx.z;
    const int i0 = it * 128, bh = b * H_ + h;
    const int tid = threadIdx.x, wid = tid >> 5, lane = tid & 31;
    const int mi = wid * 32;

    // ---- prologue staging: Qs (one row per thread), KS, Qe ----
    {
        int gi = min(i0 + tid, L_ - 1);
        const float4* src = (const float4*)(g_qp + ((size_t)bh * L_ + gi) * 8);
        ((float4*)(Qs + tid * 8))[0] = src[0];
        ((float4*)(Qs + tid * 8))[1] = src[1];
    }
    if (tid < 8) {
        float s = 0.0f;
#pragma unroll
        for (int c2 = 0; c2 < 9; c2++) s += g_ksp[((size_t)bh * 9 + c2) * 8 + tid];
        KS[tid] = s;
    }
    {
        __half* Qe = (__half*)(smem + OFF_QE);
#pragma unroll
        for (int iter = 0; iter < 2; iter++) {
            int idx = iter * 128 + tid;
            int rr = idx >> 1, c = (idx & 1) * 8;
            int gi = min(i0 + rr, L_ - 1);
            *(uint4*)(Qe + rr * 24 + c) = __ldg((const uint4*)(g_qe + ((size_t)bh * L_ + gi) * 16 + c));
        }
    }

    const int v_row = tid >> 3, v_col = (tid & 7) * 8;   // V: 4 row groups of 16
    const int k_row = tid >> 3, k_col = (tid & 7) * 8;   // Kt: 16 rows exactly

    // issue tile 0
    {
        uint32_t vh_d = sb + OFF_VH;
        uint32_t kt_d = sb + OFF_KT;
#pragma unroll
        for (int i = 0; i < 4; i++) {
            int rr = v_row + i * 16;
            cpa16(vh_d + (rr * 72 + v_col) * 2, g_vh + ((size_t)bh * L_ + rr) * 64 + v_col);
        }
        cpa16(kt_d + (k_row * 72 + k_col) * 2, g_kt + ((size_t)bh * 16 + k_row) * L_ + k_col);
        CP_COMMIT();
    }
    __syncthreads();   // Qe/Qs visible

    const int lq = lane >> 3, lr = lane & 7;
    const int a_row = lr + ((lq & 1) << 3);
    const int a_col = (lq & 2) << 2;
    const int vrow = ((lane >> 3) & 1) * 8 + lr;
    const int vcol = ((lane >> 4) & 1) * 8;

    // Q fragments: 1 per half (k=16)
    uint32_t qf[2][4];
    {
        const uint32_t qe_b = sb + OFF_QE;
#pragma unroll
        for (int hh = 0; hh < 2; hh++)
            ldmx4(qe_b + ((mi + hh * 16 + a_row) * 24 + a_col) * 2, qf[hh]);
    }

    float accv[2][8][4];
#pragma unroll
    for (int hh = 0; hh < 2; hh++)
#pragma unroll
        for (int n = 0; n < 8; n++)
#pragma unroll
            for (int c = 0; c < 4; c++) accv[hh][n][c] = 0.0f;

    const float* maskh = mask + (size_t)h * L_ * L_;
    int rc[4];
#pragma unroll
    for (int g = 0; g < 4; g++) rc[g] = min(i0 + mi + (lane >> 2) + g * 8, L_ - 1);

    for (int jt = 0; jt < 9; jt++) {
        const int j0 = jt * 64;
        const int buf = jt & 1;
        if (jt < 8) {
            const int jn = j0 + 64, nbuf = buf ^ 1;
            uint32_t vh_d = sb + OFF_VH + nbuf * VH_SZ;
            uint32_t kt_d = sb + OFF_KT + nbuf * KT_SZ;
#pragma unroll
            for (int i = 0; i < 4; i++) {
                int rr = v_row + i * 16;
                cpa16(vh_d + (rr * 72 + v_col) * 2, g_vh + ((size_t)bh * L_ + jn + rr) * 64 + v_col);
            }
            cpa16(kt_d + (k_row * 72 + k_col) * 2, g_kt + ((size_t)bh * 16 + k_row) * L_ + jn + k_col);
            CP_COMMIT();
            CP_WAIT(1);
        } else {
            CP_WAIT(0);
        }
        __syncthreads();

        const uint32_t kt_b = sb + OFF_KT + buf * KT_SZ;
        const uint32_t vh_b = sb + OFF_VH + buf * VH_SZ;

        // Kt fragments once (16 k-rows), reused by both halves
        uint32_t kb[4][4];
#pragma unroll
        for (int ntp = 0; ntp < 4; ntp++)
            ldmx4t(kt_b + (vrow * 72 + ntp * 16 + vcol) * 2, kb[ntp]);

        // S (1 MMA) + mask + pack per half
        uint32_t ah[2][4][4];
#pragma unroll
        for (int hh = 0; hh < 2; hh++) {
#pragma unroll
            for (int ntp = 0; ntp < 4; ntp++) {
#pragma unroll
                for (int e = 0; e < 2; e++) {
                    int nt = ntp * 2 + e;
                    float sc[4] = {0.0f, 0.0f, 0.0f, 0.0f};
                    mma16816(sc, qf[hh], &kb[ntp][e * 2]);
                    const float* mp0 = maskh + (size_t)rc[hh * 2] * L_ + j0 + nt * 8 + 2 * (lane & 3);
                    const float* mp1 = maskh + (size_t)rc[hh * 2 + 1] * L_ + j0 + nt * 8 + 2 * (lane & 3);
                    float2 m0 = __ldg((const float2*)mp0);
                    float2 m1 = __ldg((const float2*)mp1);
                    int ki = nt >> 1, pp = (nt & 1) * 2;
                    ah[hh][ki][pp]     = cvtf2(sc[1] * m0.y, sc[0] * m0.x);
                    ah[hh][ki][pp + 1] = cvtf2(sc[3] * m1.y, sc[2] * m1.x);
                }
            }
        }
        // AV: D += Ah*Vh
#pragma unroll
        for (int ki = 0; ki < 4; ki++) {
#pragma unroll
            for (int ntp = 0; ntp < 4; ntp++) {
                uint32_t vh4[4];
                ldmx4t(vh_b + ((ki * 16 + vrow) * 72 + ntp * 16 + vcol) * 2, vh4);
#pragma unroll
                for (int e = 0; e < 2; e++) {
                    int nt = ntp * 2 + e;
#pragma unroll
                    for (int hh = 0; hh < 2; hh++)
                        mma16816(accv[hh][nt], ah[hh][ki], &vh4[e * 2]);
                }
            }
        }
        __syncthreads();
    }

    // ---- epilogue ----
#pragma unroll
    for (int hh = 0; hh < 2; hh++) {
        int rl = mi + hh * 16 + (lane >> 2);
        int gi0 = i0 + rl, gi1 = gi0 + 8;
        float n0 = 0.0f, n1 = 0.0f;
#pragma unroll
        for (int m = 0; m < 8; m++) {
            n0 += Qs[rl * 8 + m] * KS[m];
            n1 += Qs[(rl + 8) * 8 + m] * KS[m];
        }
        float rn0 = 1.0f / n0, rn1 = 1.0f / n1;
#pragma unroll
        for (int nt = 0; nt < 8; nt++) {
            int col = nt * 8 + 2 * (lane & 3);
            if (gi0 < L_) {
                float* o0 = out + (((size_t)b * L_ + gi0) * H_ + h) * D_ + col;
                *(float2*)o0 = make_float2(accv[hh][nt][0] * rn0, accv[hh][nt][1] * rn0);
            }
            if (gi1 < L_) {
                float* o1 = out + (((size_t)b * L_ + gi1) * H_ + h) * D_ + col;
                *(float2*)o1 = make_float2(accv[hh][nt][2] * rn1, accv[hh][nt][3] * rn1);
            }
        }
    }
}

// ============================================================
extern "C" void kernel_launch(void* const* d_in, const int* in_sizes, int n_in,
                              void* d_out, int out_size) {
    const float* q    = (const float*)d_in[0];
    const float* k    = (const float*)d_in[1];
    const float* v    = (const float*)d_in[2];
    const float* proj = (const float*)d_in[3];
    const float* mask = (const float*)d_in[4];
    float* out = (float*)d_out;

    cudaFuncSetAttribute(attn_kernel, cudaFuncAttributeMaxDynamicSharedMemorySize, SMEM_SZ);

    {
        dim3 grid(NCH, H_);
        cmask_part_kernel<<<grid, 576>>>(mask);
    }
    {
        dim3 grid(9, H_, B_);
        prep_kernel<<<grid, 128>>>(q, k, v, proj);
    }
    {
        dim3 grid(5, H_, B_);
        attn_kernel<<<grid, 128, SMEM_SZ>>>(mask, out);
    }
}

// round 17
// speedup vs baseline: 1.7754x; 1.1784x over previous
#include <cuda_runtime.h>
#include <cuda_fp16.h>
#include <cstdint>

#define B_ 16
#define L_ 576
#define H_ 12
#define D_ 64
#define M_ 8
#define NUM_STAB 1e-3f
#define RATIO 0.35355339059327373f   /* 1/sqrt(M) */
#define NCH 48

// -------- scratch (device globals) --------
__device__ float g_qp[B_ * H_ * L_ * M_];
__device__ float g_cmp[NCH * H_ * L_];
__device__ float g_ksp[B_ * H_ * 9 * M_];
__device__ __align__(16) __half g_qe[B_ * H_ * L_ * 16];  // [bh][l][16]=[qh,qh]
__device__ __align__(16) __half g_kt[B_ * H_ * 16 * L_];  // [bh][k=16][l]=[kh;kl]
__device__ __align__(16) __half g_vh[B_ * H_ * L_ * 64];  // V fp16
__device__ __align__(16) __half g_mh[(size_t)H_ * L_ * L_]; // mask fp16 [h][i][j]

// -------- helpers --------
__device__ __forceinline__ void ldmx4(uint32_t addr, uint32_t* r) {
    asm volatile("ldmatrix.sync.aligned.m8n8.x4.shared.b16 {%0,%1,%2,%3}, [%4];"
                 : "=r"(r[0]), "=r"(r[1]), "=r"(r[2]), "=r"(r[3]) : "r"(addr));
}
__device__ __forceinline__ void ldmx4t(uint32_t addr, uint32_t* r) {
    asm volatile("ldmatrix.sync.aligned.m8n8.x4.trans.shared.b16 {%0,%1,%2,%3}, [%4];"
                 : "=r"(r[0]), "=r"(r[1]), "=r"(r[2]), "=r"(r[3]) : "r"(addr));
}
__device__ __forceinline__ void mma16816(float* c, const uint32_t* a, const uint32_t* b) {
    asm volatile("mma.sync.aligned.m16n8k16.row.col.f32.f16.f16.f32 "
                 "{%0,%1,%2,%3}, {%4,%5,%6,%7}, {%8,%9}, {%0,%1,%2,%3};"
                 : "+f"(c[0]), "+f"(c[1]), "+f"(c[2]), "+f"(c[3])
                 : "r"(a[0]), "r"(a[1]), "r"(a[2]), "r"(a[3]), "r"(b[0]), "r"(b[1]));
}
__device__ __forceinline__ uint32_t cvtf2(float hi, float lo) {
    uint32_t r; asm("cvt.rn.f16x2.f32 %0, %1, %2;" : "=r"(r) : "f"(hi), "f"(lo)); return r;
}
__device__ __forceinline__ uint32_t smem_u32(const void* p) {
    return (uint32_t)__cvta_generic_to_shared(p);
}
__device__ __forceinline__ void cpa16(uint32_t dst, const void* src) {
    asm volatile("cp.async.cg.shared.global [%0], [%1], 16;" :: "r"(dst), "l"(src));
}
#define CP_COMMIT() asm volatile("cp.async.commit_group;" ::: "memory")
#define CP_WAIT(n)  asm volatile("cp.async.wait_group %0;" :: "n"(n) : "memory")

// smem layout (dynamic)
#define VH_SZ 9216    /* 64*72*2 */
#define KT_SZ 2304    /* 16*72*2 */
#define MS_SZ 18432   /* 128*72*2 */
#define OFF_VH 0
#define OFF_KT (2 * VH_SZ)                     /* 18432 */
#define OFF_MS (OFF_KT + 2 * KT_SZ)            /* 23040 */
#define OFF_QE (OFF_MS + 2 * MS_SZ)            /* 59904; 128*24*2 = 6144 */
#define OFF_QS (OFF_QE + 6144)                 /* 66048; 128*8*4 = 4096 */
#define OFF_KS (OFF_QS + 4096)
#define SMEM_SZ (OFF_KS + 32)

// ============================================================
// Kernel 1: partial column sums of mask + fp16 mask copy
// 48 chunks x 12 rows (576 CTAs)
// ============================================================
__global__ void __launch_bounds__(576) cmask_part_kernel(const float* __restrict__ mask) {
    int j  = threadIdx.x;
    int h  = blockIdx.y, ch = blockIdx.x;
    const float* mp = mask + ((size_t)h * L_ + ch * 12) * L_ + j;
    __half* mh = g_mh + ((size_t)h * L_ + ch * 12) * L_ + j;
    float s = 0.0f;
#pragma unroll
    for (int i = 0; i < 12; i++) {
        float v = mp[(size_t)i * L_];
        s += v;
        mh[(size_t)i * L_] = __float2half_rn(v);
    }
    g_cmp[(ch * H_ + h) * L_ + j] = s;
}

// ============================================================
// Kernel 2: fused prep (fp16; Qe=[qh,qh], Kt=[kh;kl], V hi only)
// ============================================================
__global__ void __launch_bounds__(128) prep_kernel(const float* __restrict__ q,
                                                   const float* __restrict__ k,
                                                   const float* __restrict__ v,
                                                   const float* __restrict__ proj) {
    __shared__ float ps[8][68];
    __shared__ float xs[64][68];
    __shared__ unsigned short kt[16][64];
    __shared__ float red[64][8];
    __shared__ float cm[64];

    const int ch = blockIdx.x, h = blockIdx.y, b = blockIdx.z;
    const int bh = b * H_ + h, l0 = ch * 64;
    const int tid = threadIdx.x;
    const int r = tid >> 1, hf = tid & 1;

    {
        float4 pv = ((const float4*)proj)[tid];
        ps[tid >> 4][(tid & 15) * 4 + 0] = pv.x;
        ps[tid >> 4][(tid & 15) * 4 + 1] = pv.y;
        ps[tid >> 4][(tid & 15) * 4 + 2] = pv.z;
        ps[tid >> 4][(tid & 15) * 4 + 3] = pv.w;
    }
    if (tid < 64) {
        float s = 0.0f;
#pragma unroll
        for (int c2 = 0; c2 < NCH; c2++) s += g_cmp[(c2 * H_ + h) * L_ + l0 + tid];
        cm[tid] = s;
    }

    // ---------- Q ----------
#pragma unroll
    for (int iter = 0; iter < 8; iter++) {
        int idx = iter * 128 + tid;
        int rr = idx >> 4, c4 = idx & 15;
        float4 val = __ldg((const float4*)(q + (((size_t)b * L_ + l0 + rr) * H_ + h) * D_ + c4 * 4));
        *(float4*)&xs[rr][c4 * 4] = val;
    }
    __syncthreads();
    {
        float f[4];
#pragma unroll
        for (int e = 0; e < 4; e++) {
            int m = hf * 4 + e;
            float acc = 0.0f;
#pragma unroll
            for (int i = 0; i < 16; i++) {
                float4 a = *(const float4*)&xs[r][i * 4];
                float4 p = *(const float4*)&ps[m][i * 4];
                acc += a.x * p.x + a.y * p.y + a.z * p.z + a.w * p.w;
            }
            f[e] = fmaxf(RATIO * acc, 0.0f) + NUM_STAB;
        }
        *(float4*)(g_qp + ((size_t)bh * L_ + l0 + r) * 8 + hf * 4) = make_float4(f[0], f[1], f[2], f[3]);
        uint32_t hi0 = cvtf2(f[1], f[0]);
        uint32_t hi1 = cvtf2(f[3], f[2]);
        __half* qr = g_qe + ((size_t)bh * L_ + l0 + r) * 16;
        *(uint2*)(qr + hf * 4)     = make_uint2(hi0, hi1);
        *(uint2*)(qr + 8 + hf * 4) = make_uint2(hi0, hi1);
    }
    __syncthreads();

    // ---------- K ----------
#pragma unroll
    for (int iter = 0; iter < 8; iter++) {
        int idx = iter * 128 + tid;
        int rr = idx >> 4, c4 = idx & 15;
        float4 val = __ldg((const float4*)(k + (((size_t)b * L_ + l0 + rr) * H_ + h) * D_ + c4 * 4));
        *(float4*)&xs[rr][c4 * 4] = val;
    }
    __syncthreads();
    {
        float cmv = cm[r];
#pragma unroll
        for (int e = 0; e < 4; e++) {
            int m = hf * 4 + e;
            float acc = 0.0f;
#pragma unroll
            for (int i = 0; i < 16; i++) {
                float4 a = *(const float4*)&xs[r][i * 4];
                float4 p = *(const float4*)&ps[m][i * 4];
                acc += a.x * p.x + a.y * p.y + a.z * p.z + a.w * p.w;
            }
            float f = fmaxf(RATIO * acc, 0.0f) + NUM_STAB;
            __half hh = __float2half_rn(f);
            unsigned short hs = *(unsigned short*)&hh;
            __half hl = __float2half_rn(f - __half2float(hh));
            unsigned short ls = *(unsigned short*)&hl;
            int kk = hf * 4 + e;
            kt[kk][r]     = hs;
            kt[kk + 8][r] = ls;
            red[r][m] = cmv * f;
        }
    }
    __syncthreads();
    {
        int kk = tid >> 3, c = (tid & 7) * 8;
        *(uint4*)(g_kt + ((size_t)bh * 16 + kk) * L_ + l0 + c) = *(const uint4*)&kt[kk][c];
    }
    if (tid < 8) {
        float s = 0.0f;
#pragma unroll 16
        for (int i = 0; i < 64; i++) s += red[i][tid];
        g_ksp[((size_t)bh * 9 + ch) * 8 + tid] = s;
    }

    // ---------- V (hi only) ----------
#pragma unroll
    for (int iter = 0; iter < 8; iter++) {
        int idx = iter * 128 + tid;
        int rr = idx >> 4, c4 = idx & 15;
        const float4 vv = __ldg((const float4*)(v + (((size_t)b * L_ + l0 + rr) * H_ + h) * D_ + c4 * 4));
        uint32_t h01 = cvtf2(vv.y, vv.x);
        uint32_t h23 = cvtf2(vv.w, vv.z);
        size_t o = ((size_t)bh * L_ + l0 + rr) * 64 + c4 * 4;
        *(uint2*)(g_vh + o) = make_uint2(h01, h23);
    }
}

// ============================================================
// Kernel 3: fused attention. grid (5, H, B), 128 thr / 4 warps.
// Warp tile M=32; cp.async double-buffered V/Kt/mask(fp16).
// ============================================================
__global__ void __launch_bounds__(128, 3)
attn_kernel(float* __restrict__ out) {
    extern __shared__ char smem[];
    const uint32_t sb = smem_u32(smem);
    float* Qs = (float*)(smem + OFF_QS);
    float* KS = (float*)(smem + OFF_KS);

    const int it = blockIdx.x, h = blockIdx.y, b = blockIdx.z;
    const int i0 = it * 128, bh = b * H_ + h;
    const int tid = threadIdx.x, wid = tid >> 5, lane = tid & 31;
    const int mi = wid * 32;

    // ---- prologue staging: Qs (one row per thread), KS, Qe ----
    {
        int gi = min(i0 + tid, L_ - 1);
        const float4* src = (const float4*)(g_qp + ((size_t)bh * L_ + gi) * 8);
        ((float4*)(Qs + tid * 8))[0] = src[0];
        ((float4*)(Qs + tid * 8))[1] = src[1];
    }
    if (tid < 8) {
        float s = 0.0f;
#pragma unroll
        for (int c2 = 0; c2 < 9; c2++) s += g_ksp[((size_t)bh * 9 + c2) * 8 + tid];
        KS[tid] = s;
    }
    {
        __half* Qe = (__half*)(smem + OFF_QE);
#pragma unroll
        for (int iter = 0; iter < 2; iter++) {
            int idx = iter * 128 + tid;
            int rr = idx >> 1, c = (idx & 1) * 8;
            int gi = min(i0 + rr, L_ - 1);
            *(uint4*)(Qe + rr * 24 + c) = __ldg((const uint4*)(g_qe + ((size_t)bh * L_ + gi) * 16 + c));
        }
    }

    const int v_row = tid >> 3, v_col = (tid & 7) * 8;   // V: 4 row groups of 16
    const int k_row = tid >> 3, k_col = (tid & 7) * 8;   // Kt: 16 rows exactly
    const int m_row = tid >> 3, m_col = (tid & 7) * 8;   // mask: 8 row groups of 16

    const __half* mhh = g_mh + (size_t)h * L_ * L_;
    // clamped global rows for mask staging (fixed per thread)
    int mg[8];
#pragma unroll
    for (int g = 0; g < 8; g++) mg[g] = min(i0 + m_row + g * 16, L_ - 1);

    // issue tile 0
    {
        uint32_t vh_d = sb + OFF_VH;
        uint32_t kt_d = sb + OFF_KT;
        uint32_t ms_d = sb + OFF_MS;
#pragma unroll
        for (int i = 0; i < 4; i++) {
            int rr = v_row + i * 16;
            cpa16(vh_d + (rr * 72 + v_col) * 2, g_vh + ((size_t)bh * L_ + rr) * 64 + v_col);
        }
        cpa16(kt_d + (k_row * 72 + k_col) * 2, g_kt + ((size_t)bh * 16 + k_row) * L_ + k_col);
#pragma unroll
        for (int g = 0; g < 8; g++) {
            int rr = m_row + g * 16;
            cpa16(ms_d + (rr * 72 + m_col) * 2, mhh + (size_t)mg[g] * L_ + m_col);
        }
        CP_COMMIT();
    }
    __syncthreads();   // Qe/Qs visible

    const int lq = lane >> 3, lr = lane & 7;
    const int a_row = lr + ((lq & 1) << 3);
    const int a_col = (lq & 2) << 2;
    const int vrow = ((lane >> 3) & 1) * 8 + lr;
    const int vcol = ((lane >> 4) & 1) * 8;

    // Q fragments: 1 per half (k=16)
    uint32_t qf[2][4];
    {
        const uint32_t qe_b = sb + OFF_QE;
#pragma unroll
        for (int hh = 0; hh < 2; hh++)
            ldmx4(qe_b + ((mi + hh * 16 + a_row) * 24 + a_col) * 2, qf[hh]);
    }

    float accv[2][8][4];
#pragma unroll
    for (int hh = 0; hh < 2; hh++)
#pragma unroll
        for (int n = 0; n < 8; n++)
#pragma unroll
            for (int c = 0; c < 4; c++) accv[hh][n][c] = 0.0f;

    for (int jt = 0; jt < 9; jt++) {
        const int j0 = jt * 64;
        const int buf = jt & 1;
        if (jt < 8) {
            const int jn = j0 + 64, nbuf = buf ^ 1;
            uint32_t vh_d = sb + OFF_VH + nbuf * VH_SZ;
            uint32_t kt_d = sb + OFF_KT + nbuf * KT_SZ;
            uint32_t ms_d = sb + OFF_MS + nbuf * MS_SZ;
#pragma unroll
            for (int i = 0; i < 4; i++) {
                int rr = v_row + i * 16;
                cpa16(vh_d + (rr * 72 + v_col) * 2, g_vh + ((size_t)bh * L_ + jn + rr) * 64 + v_col);
            }
            cpa16(kt_d + (k_row * 72 + k_col) * 2, g_kt + ((size_t)bh * 16 + k_row) * L_ + jn + k_col);
#pragma unroll
            for (int g = 0; g < 8; g++) {
                int rr = m_row + g * 16;
                cpa16(ms_d + (rr * 72 + m_col) * 2, mhh + (size_t)mg[g] * L_ + jn + m_col);
            }
            CP_COMMIT();
            CP_WAIT(1);
        } else {
            CP_WAIT(0);
        }
        __syncthreads();

        const uint32_t kt_b = sb + OFF_KT + buf * KT_SZ;
        const uint32_t vh_b = sb + OFF_VH + buf * VH_SZ;
        const __half* Msb = (const __half*)(smem + OFF_MS + buf * MS_SZ);

        // Kt fragments once (16 k-rows), reused by both halves
        uint32_t kb[4][4];
#pragma unroll
        for (int ntp = 0; ntp < 4; ntp++)
            ldmx4t(kt_b + (vrow * 72 + ntp * 16 + vcol) * 2, kb[ntp]);

        // S (1 MMA) + mask (smem fp16) + pack per half
        uint32_t ah[2][4][4];
#pragma unroll
        for (int hh = 0; hh < 2; hh++) {
            const int r0l = mi + hh * 16 + (lane >> 2);
#pragma unroll
            for (int ntp = 0; ntp < 4; ntp++) {
#pragma unroll
                for (int e = 0; e < 2; e++) {
                    int nt = ntp * 2 + e;
                    float sc[4] = {0.0f, 0.0f, 0.0f, 0.0f};
                    mma16816(sc, qf[hh], &kb[ntp][e * 2]);
                    int coff = nt * 8 + 2 * (lane & 3);
                    __half2 hm0 = *(const __half2*)(Msb + r0l * 72 + coff);
                    __half2 hm1 = *(const __half2*)(Msb + (r0l + 8) * 72 + coff);
                    float2 m0 = __half22float2(hm0);
                    float2 m1 = __half22float2(hm1);
                    int ki = nt >> 1, pp = (nt & 1) * 2;
                    ah[hh][ki][pp]     = cvtf2(sc[1] * m0.y, sc[0] * m0.x);
                    ah[hh][ki][pp + 1] = cvtf2(sc[3] * m1.y, sc[2] * m1.x);
                }
            }
        }
        // AV: D += Ah*Vh
#pragma unroll
        for (int ki = 0; ki < 4; ki++) {
#pragma unroll
            for (int ntp = 0; ntp < 4; ntp++) {
                uint32_t vh4[4];
                ldmx4t(vh_b + ((ki * 16 + vrow) * 72 + ntp * 16 + vcol) * 2, vh4);
#pragma unroll
                for (int e = 0; e < 2; e++) {
                    int nt = ntp * 2 + e;
#pragma unroll
                    for (int hh = 0; hh < 2; hh++)
                        mma16816(accv[hh][nt], ah[hh][ki], &vh4[e * 2]);
                }
            }
        }
        __syncthreads();
    }

    // ---- epilogue ----
#pragma unroll
    for (int hh = 0; hh < 2; hh++) {
        int rl = mi + hh * 16 + (lane >> 2);
        int gi0 = i0 + rl, gi1 = gi0 + 8;
        float n0 = 0.0f, n1 = 0.0f;
#pragma unroll
        for (int m = 0; m < 8; m++) {
            n0 += Qs[rl * 8 + m] * KS[m];
            n1 += Qs[(rl + 8) * 8 + m] * KS[m];
        }
        float rn0 = 1.0f / n0, rn1 = 1.0f / n1;
#pragma unroll
        for (int nt = 0; nt < 8; nt++) {
            int col = nt * 8 + 2 * (lane & 3);
            if (gi0 < L_) {
                float* o0 = out + (((size_t)b * L_ + gi0) * H_ + h) * D_ + col;
                *(float2*)o0 = make_float2(accv[hh][nt][0] * rn0, accv[hh][nt][1] * rn0);
            }
            if (gi1 < L_) {
                float* o1 = out + (((size_t)b * L_ + gi1) * H_ + h) * D_ + col;
                *(float2*)o1 = make_float2(accv[hh][nt][2] * rn1, accv[hh][nt][3] * rn1);
            }
        }
    }
}

// ============================================================
extern "C" void kernel_launch(void* const* d_in, const int* in_sizes, int n_in,
                              void* d_out, int out_size) {
    const float* q    = (const float*)d_in[0];
    const float* k    = (const float*)d_in[1];
    const float* v    = (const float*)d_in[2];
    const float* proj = (const float*)d_in[3];
    const float* mask = (const float*)d_in[4];
    float* out = (float*)d_out;

    cudaFuncSetAttribute(attn_kernel, cudaFuncAttributeMaxDynamicSharedMemorySize, SMEM_SZ);

    {
        dim3 grid(NCH, H_);
        cmask_part_kernel<<<grid, 576>>>(mask);
    }
    {
        dim3 grid(9, H_, B_);
        prep_kernel<<<grid, 128>>>(q, k, v, proj);
    }
    {
        dim3 grid(5, H_, B_);
        attn_kernel<<<grid, 128, SMEM_SZ>>>(out);
    }
}